// round 12
// baseline (speedup 1.0000x reference)
#include <cuda_runtime.h>
#include <cuda_fp16.h>
#include <cstdint>
#include <math.h>

#define BB 64
#define TT 1380
#define TTP 1384
#define XD 96
#define HD 192
#define CN 345

// ---------------- scratch ----------------
static __device__ float g_S [(size_t)BB * CN * TT];
static __device__ float g_rmax[BB * CN];
static __device__ float g_rinv[BB * CN];
static __device__ __half g_W2h[(size_t)CN * TTP],        g_W2l[(size_t)CN * TTP];
static __device__ __half g_XTh[(size_t)BB * XD * TTP],   g_XTl[(size_t)BB * XD * TTP];
static __device__ __half g_Hh [(size_t)BB * TT * HD],    g_Hl [(size_t)BB * TT * HD];
static __device__ __half g_HTh[(size_t)BB * HD * TTP],   g_HTl[(size_t)BB * HD * TTP];
static __device__ __half g_W1Th[(size_t)HD * XD],        g_W1Tl[(size_t)HD * XD];
static __device__ __half g_M1h[(size_t)BB * CN * XD],    g_M1l[(size_t)BB * CN * XD];
static __device__ __half g_Gh [(size_t)BB * CN * HD],    g_Gl [(size_t)BB * CN * HD];

// ---------------- PTX helpers ----------------
__device__ __forceinline__ uint32_t smem_u32(const void* p) {
    uint32_t a;
    asm("{ .reg .u64 t; cvta.to.shared.u64 t, %1; cvt.u32.u64 %0, t; }" : "=r"(a) : "l"(p));
    return a;
}
__device__ __forceinline__ void cpa(uint32_t dst, const void* src, int bytes) {
    asm volatile("cp.async.cg.shared.global [%0], [%1], 16, %2;"
                 :: "r"(dst), "l"(src), "r"(bytes) : "memory");
}
#define CP_COMMIT() asm volatile("cp.async.commit_group;" ::: "memory")
#define CP_WAIT1()  asm volatile("cp.async.wait_group 1;" ::: "memory")
#define CP_WAIT0()  asm volatile("cp.async.wait_group 0;" ::: "memory")

__device__ __forceinline__ void mma16(float* d, const uint32_t* a, uint32_t b0, uint32_t b1) {
    asm volatile(
        "mma.sync.aligned.m16n8k16.row.col.f32.f16.f16.f32 "
        "{%0,%1,%2,%3}, {%4,%5,%6,%7}, {%8,%9}, {%0,%1,%2,%3};"
        : "+f"(d[0]), "+f"(d[1]), "+f"(d[2]), "+f"(d[3])
        : "r"(a[0]), "r"(a[1]), "r"(a[2]), "r"(a[3]), "r"(b0), "r"(b1));
}
__device__ __forceinline__ __half2 split_hi(float x, float y, __half2& lo) {
    const __half hx = __float2half(x), hy = __float2half(y);
    lo = __halves2half2(__float2half(x - __half2float(hx)),
                        __float2half(y - __half2float(hy)));
    return __halves2half2(hx, hy);
}

#define ROWST 40

// ---------------------------------------------------------------------------
// fp16 3-pass split GEMM (unchanged R8/R10 mainloop)
// ---------------------------------------------------------------------------
template <int BN, int NT, int OUT>
__global__ void __launch_bounds__(NT, 2) gemm_h3(
    const __half* __restrict__ Agh, const __half* __restrict__ Agl,
    const __half* __restrict__ Bgh, const __half* __restrict__ Bgl,
    float* __restrict__ Cf, __half* __restrict__ Ch, __half* __restrict__ Cl,
    int M, int N, int K, int lda, int ldb, int ldc,
    long sA, long sB, long sC, float alpha)
{
    constexpr int WCOLS = BN / 32;
    constexpr int ARR_A = 128 * ROWST;
    constexpr int ARR_B = BN * ROWST;
    constexpr int STG = 2 * ARR_A + 2 * ARR_B;

    extern __shared__ __half sm[];
    const uint32_t sb = smem_u32(sm);
    const int tid = threadIdx.x;
    const int wid = tid >> 5, lane = tid & 31;
    const int wm = wid / WCOLS, wn = wid % WCOLS;
    const int grp = lane >> 2, qid = lane & 3;
    const int b = blockIdx.z;

    Agh += (long)b * sA; Agl += (long)b * sA;
    Bgh += (long)b * sB; Bgl += (long)b * sB;
    if (OUT == 0) Cf += (long)b * sC;

    const int m0 = blockIdx.y * 128;
    const int n0 = blockIdx.x * BN;

    int mtN = (M - m0 - wm * 64 + 15) >> 4;
    if (mtN < 0) mtN = 0; if (mtN > 4) mtN = 4;
    int ntN = (N - n0 - wn * 32 + 7) >> 3;
    if (ntN < 0) ntN = 0; if (ntN > 4) ntN = 4;

    float acc[4][4][4];
#pragma unroll
    for (int i = 0; i < 4; i++)
#pragma unroll
        for (int j = 0; j < 4; j++)
#pragma unroll
            for (int r = 0; r < 4; r++) acc[i][j][r] = 0.f;

    auto ldst = [&](int kb) {
        const uint32_t base = sb + (uint32_t)(kb & 1) * (STG * 2);
        const int k0 = kb * 32;
        for (int f = tid; f < 128 * 4; f += NT) {
            const int row = f >> 2, ch = f & 3;
            const int gk = k0 + ch * 8;
            int kbytes = (K - gk) * 2;
            if (kbytes > 16) kbytes = 16;
            if (kbytes < 0) kbytes = 0;
            const int gm = m0 + row;
            const int bytes = (gm < M) ? kbytes : 0;
            const long off = bytes ? ((long)gm * lda + gk) : 0;
            const uint32_t doff = (uint32_t)(row * ROWST + ch * 8) * 2;
            cpa(base + doff, Agh + off, bytes);
            cpa(base + ARR_A * 2 + doff, Agl + off, bytes);
        }
        for (int f = tid; f < BN * 4; f += NT) {
            const int row = f >> 2, ch = f & 3;
            const int gk = k0 + ch * 8;
            int kbytes = (K - gk) * 2;
            if (kbytes > 16) kbytes = 16;
            if (kbytes < 0) kbytes = 0;
            const int gn = n0 + row;
            const int bytes = (gn < N) ? kbytes : 0;
            const long off = bytes ? ((long)gn * ldb + gk) : 0;
            const uint32_t doff = (uint32_t)(row * ROWST + ch * 8) * 2;
            cpa(base + 2 * ARR_A * 2 + doff, Bgh + off, bytes);
            cpa(base + 2 * ARR_A * 2 + ARR_B * 2 + doff, Bgl + off, bytes);
        }
    };

    const int nb = (K + 31) >> 5;
    ldst(0); CP_COMMIT();

    for (int kb = 0; kb < nb; kb++) {
        if (kb + 1 < nb) { ldst(kb + 1); CP_COMMIT(); CP_WAIT1(); }
        else             { CP_WAIT0(); }
        __syncthreads();

        const __half* Ash = sm + (kb & 1) * STG;
        const __half* Asl = Ash + ARR_A;
        const __half* Bsh = Ash + 2 * ARR_A;
        const __half* Bsl = Bsh + ARR_B;

#pragma unroll
        for (int kc = 0; kc < 2; kc++) {
            const int kf = kc * 16;
            uint32_t ah[4][4], al[4][4];
#pragma unroll
            for (int mt = 0; mt < 4; mt++) {
                if (mt < mtN) {
                    const int r0 = wm * 64 + mt * 16 + grp;
                    ah[mt][0] = *(const uint32_t*)(Ash + (r0    ) * ROWST + kf     + 2 * qid);
                    ah[mt][1] = *(const uint32_t*)(Ash + (r0 + 8) * ROWST + kf     + 2 * qid);
                    ah[mt][2] = *(const uint32_t*)(Ash + (r0    ) * ROWST + kf + 8 + 2 * qid);
                    ah[mt][3] = *(const uint32_t*)(Ash + (r0 + 8) * ROWST + kf + 8 + 2 * qid);
                    al[mt][0] = *(const uint32_t*)(Asl + (r0    ) * ROWST + kf     + 2 * qid);
                    al[mt][1] = *(const uint32_t*)(Asl + (r0 + 8) * ROWST + kf     + 2 * qid);
                    al[mt][2] = *(const uint32_t*)(Asl + (r0    ) * ROWST + kf + 8 + 2 * qid);
                    al[mt][3] = *(const uint32_t*)(Asl + (r0 + 8) * ROWST + kf + 8 + 2 * qid);
                }
            }
#pragma unroll
            for (int nt = 0; nt < 4; nt++) {
                if (nt < ntN) {
                    const int c0 = wn * 32 + nt * 8 + grp;
                    const uint32_t bh0 = *(const uint32_t*)(Bsh + c0 * ROWST + kf     + 2 * qid);
                    const uint32_t bh1 = *(const uint32_t*)(Bsh + c0 * ROWST + kf + 8 + 2 * qid);
                    const uint32_t bl0 = *(const uint32_t*)(Bsl + c0 * ROWST + kf     + 2 * qid);
                    const uint32_t bl1 = *(const uint32_t*)(Bsl + c0 * ROWST + kf + 8 + 2 * qid);
#pragma unroll
                    for (int mt = 0; mt < 4; mt++) {
                        if (mt < mtN) {
                            mma16(acc[mt][nt], ah[mt], bh0, bh1);
                            mma16(acc[mt][nt], ah[mt], bl0, bl1);
                            mma16(acc[mt][nt], al[mt], bh0, bh1);
                        }
                    }
                }
            }
        }
        __syncthreads();
    }

#pragma unroll
    for (int mt = 0; mt < 4; mt++) {
        if (mt >= mtN) break;
#pragma unroll
        for (int nt = 0; nt < 4; nt++) {
            if (nt >= ntN) break;
            const int gmA = m0 + wm * 64 + mt * 16 + grp;
            const int gn  = n0 + wn * 32 + nt * 8 + 2 * qid;
            if (gn + 2 > N) continue;
#pragma unroll
            for (int half_ = 0; half_ < 2; half_++) {
                const int gm = gmA + half_ * 8;
                if (gm >= M) continue;
                const float v0 = acc[mt][nt][half_ * 2 + 0] * alpha;
                const float v1 = acc[mt][nt][half_ * 2 + 1] * alpha;
                if (OUT == 0) {
                    *reinterpret_cast<float2*>(Cf + (long)gm * ldc + gn) =
                        make_float2(v0, v1);
                } else if (OUT == 1) {
                    __half2 lo, hi = split_hi(v0, v1, lo);
                    *reinterpret_cast<__half2*>(Ch + (long)gm * ldc + gn) = hi;
                    *reinterpret_cast<__half2*>(Cl + (long)gm * ldc + gn) = lo;
                } else {
                    const int b1 = gn / XD, x = gn - b1 * XD;
                    const long addr = (long)b1 * sC + (long)gm * XD + x;
                    __half2 lo, hi = split_hi(v0, v1, lo);
                    *reinterpret_cast<__half2*>(Ch + addr) = hi;
                    *reinterpret_cast<__half2*>(Cl + addr) = lo;
                }
            }
        }
    }
}

// ---------------------------------------------------------------------------
// K5 fused: out[b] = softmax-rows(S[b]) @ H[b], producer/consumer warps.
// 6 consumer warps (2x3, warp tile 64x32 over BN=96) + 2 producer warps.
// Producers: cp.async HT hi/lo (B side) + LDG S fp32 -> exp -> split -> STS.
// ---------------------------------------------------------------------------
__global__ void __launch_bounds__(256, 2) gemm_k5_fused(
    const float* __restrict__ Sg,
    const float* __restrict__ rmaxA, const float* __restrict__ rinvA,
    const __half* __restrict__ Bgh, const __half* __restrict__ Bgl,
    float* __restrict__ Cf)
{
    constexpr int BN = 96, WCOLS = 3;
    constexpr int ARR_A = 128 * ROWST;
    constexpr int ARR_B = BN * ROWST;
    constexpr int STG = 2 * ARR_A + 2 * ARR_B;
    const int M = CN, N = HD, K = TT;

    extern __shared__ __half sm[];
    const uint32_t sb = smem_u32(sm);
    const int tid = threadIdx.x;
    const int wid = tid >> 5, lane = tid & 31;
    const int b = blockIdx.z;

    const float* S = Sg + (long)b * CN * TT;
    const __half* BghB = Bgh + (long)b * HD * TTP;
    const __half* BglB = Bgl + (long)b * HD * TTP;
    float* C = Cf + (long)b * CN * HD;
    const float* rmax = rmaxA + (long)b * CN;
    const float* rinv = rinvA + (long)b * CN;

    const int m0 = blockIdx.y * 128;
    const int n0 = blockIdx.x * BN;
    const int nb = (K + 31) >> 5;   // 44

    if (wid >= 6) {
        // ---------------- producer warps ----------------
        const int pid = tid - 192;   // 0..63
        auto fill = [&](int kb) {
            const uint32_t base = sb + (uint32_t)(kb & 1) * (STG * 2);
            const int k0 = kb * 32;
            // B side: cp.async HT hi/lo (96 rows x 4 chunks = 384 / 64 lanes)
#pragma unroll
            for (int i = 0; i < 6; i++) {
                const int f = pid + i * 64;
                const int row = f >> 2, ch = f & 3;
                const int gk = k0 + ch * 8;
                int kbytes = (K - gk) * 2;
                if (kbytes > 16) kbytes = 16;
                if (kbytes < 0) kbytes = 0;
                const int gn = n0 + row;
                const int bytes = (gn < N) ? kbytes : 0;
                const long off = bytes ? ((long)gn * TTP + gk) : 0;
                const uint32_t doff = (uint32_t)(row * ROWST + ch * 8) * 2;
                cpa(base + 2 * ARR_A * 2 + doff, BghB + off, bytes);
                cpa(base + 2 * ARR_A * 2 + ARR_B * 2 + doff, BglB + off, bytes);
            }
            CP_COMMIT();
            // A side: LDG fp32 S (batch all 16 float4 first for MLP)
            float4 va[16];
#pragma unroll
            for (int i = 0; i < 16; i++) {
                const int f = pid + i * 64;          // 0..1023
                const int row = f >> 3, c4 = f & 7;
                const int gm = m0 + row, gk = k0 + c4 * 4;
                float4 v = make_float4(0.f, 0.f, 0.f, 0.f);
                if (gm < M && gk + 4 <= K)
                    v = *reinterpret_cast<const float4*>(S + (long)gm * TT + gk);
                va[i] = v;
            }
            __half* Ash = sm + (kb & 1) * STG;
            __half* Asl = Ash + ARR_A;
#pragma unroll
            for (int i = 0; i < 16; i++) {
                const int f = pid + i * 64;
                const int row = f >> 3, c4 = f & 7;
                const int gm = m0 + row, gk = k0 + c4 * 4;
                float4 v = va[i];
                if (gm < M && gk + 4 <= K) {
                    const float mx = rmax[gm], rv = rinv[gm];
                    v.x = __expf(v.x - mx) * rv;
                    v.y = __expf(v.y - mx) * rv;
                    v.z = __expf(v.z - mx) * rv;
                    v.w = __expf(v.w - mx) * rv;
                } else {
                    v = make_float4(0.f, 0.f, 0.f, 0.f);
                }
                __half2 l0, h0 = split_hi(v.x, v.y, l0);
                __half2 l1, h1 = split_hi(v.z, v.w, l1);
                __half2* ph = reinterpret_cast<__half2*>(Ash + row * ROWST + c4 * 4);
                __half2* pl = reinterpret_cast<__half2*>(Asl + row * ROWST + c4 * 4);
                ph[0] = h0; ph[1] = h1;
                pl[0] = l0; pl[1] = l1;
            }
            CP_WAIT0();
        };

        fill(0);
        __syncthreads();
        for (int kb = 0; kb < nb; kb++) {
            if (kb + 1 < nb) fill(kb + 1);
            __syncthreads();
        }
        return;
    }

    // ---------------- consumer warps (wid 0..5) ----------------
    const int wm = wid / WCOLS, wn = wid % WCOLS;
    const int grp = lane >> 2, qid = lane & 3;

    int mtN = (M - m0 - wm * 64 + 15) >> 4;
    if (mtN < 0) mtN = 0; if (mtN > 4) mtN = 4;
    int ntN = (N - n0 - wn * 32 + 7) >> 3;
    if (ntN < 0) ntN = 0; if (ntN > 4) ntN = 4;

    float acc[4][4][4];
#pragma unroll
    for (int i = 0; i < 4; i++)
#pragma unroll
        for (int j = 0; j < 4; j++)
#pragma unroll
            for (int r = 0; r < 4; r++) acc[i][j][r] = 0.f;

    __syncthreads();   // matches producer's post-fill(0) barrier

    for (int kb = 0; kb < nb; kb++) {
        const __half* Ash = sm + (kb & 1) * STG;
        const __half* Asl = Ash + ARR_A;
        const __half* Bsh = Ash + 2 * ARR_A;
        const __half* Bsl = Bsh + ARR_B;

#pragma unroll
        for (int kc = 0; kc < 2; kc++) {
            const int kf = kc * 16;
            uint32_t ah[4][4], al[4][4];
#pragma unroll
            for (int mt = 0; mt < 4; mt++) {
                if (mt < mtN) {
                    const int r0 = wm * 64 + mt * 16 + grp;
                    ah[mt][0] = *(const uint32_t*)(Ash + (r0    ) * ROWST + kf     + 2 * qid);
                    ah[mt][1] = *(const uint32_t*)(Ash + (r0 + 8) * ROWST + kf     + 2 * qid);
                    ah[mt][2] = *(const uint32_t*)(Ash + (r0    ) * ROWST + kf + 8 + 2 * qid);
                    ah[mt][3] = *(const uint32_t*)(Ash + (r0 + 8) * ROWST + kf + 8 + 2 * qid);
                    al[mt][0] = *(const uint32_t*)(Asl + (r0    ) * ROWST + kf     + 2 * qid);
                    al[mt][1] = *(const uint32_t*)(Asl + (r0 + 8) * ROWST + kf     + 2 * qid);
                    al[mt][2] = *(const uint32_t*)(Asl + (r0    ) * ROWST + kf + 8 + 2 * qid);
                    al[mt][3] = *(const uint32_t*)(Asl + (r0 + 8) * ROWST + kf + 8 + 2 * qid);
                }
            }
#pragma unroll
            for (int nt = 0; nt < 4; nt++) {
                if (nt < ntN) {
                    const int c0 = wn * 32 + nt * 8 + grp;
                    const uint32_t bh0 = *(const uint32_t*)(Bsh + c0 * ROWST + kf     + 2 * qid);
                    const uint32_t bh1 = *(const uint32_t*)(Bsh + c0 * ROWST + kf + 8 + 2 * qid);
                    const uint32_t bl0 = *(const uint32_t*)(Bsl + c0 * ROWST + kf     + 2 * qid);
                    const uint32_t bl1 = *(const uint32_t*)(Bsl + c0 * ROWST + kf + 8 + 2 * qid);
#pragma unroll
                    for (int mt = 0; mt < 4; mt++) {
                        if (mt < mtN) {
                            mma16(acc[mt][nt], ah[mt], bh0, bh1);
                            mma16(acc[mt][nt], ah[mt], bl0, bl1);
                            mma16(acc[mt][nt], al[mt], bh0, bh1);
                        }
                    }
                }
            }
        }
        __syncthreads();
    }

#pragma unroll
    for (int mt = 0; mt < 4; mt++) {
        if (mt >= mtN) break;
#pragma unroll
        for (int nt = 0; nt < 4; nt++) {
            if (nt >= ntN) break;
            const int gmA = m0 + wm * 64 + mt * 16 + grp;
            const int gn  = n0 + wn * 32 + nt * 8 + 2 * qid;
            if (gn + 2 > N) continue;
#pragma unroll
            for (int half_ = 0; half_ < 2; half_++) {
                const int gm = gmA + half_ * 8;
                if (gm >= M) continue;
                *reinterpret_cast<float2*>(C + (long)gm * HD + gn) =
                    make_float2(acc[mt][nt][half_ * 2 + 0], acc[mt][nt][half_ * 2 + 1]);
            }
        }
    }
}

// ---------------------------------------------------------------------------
// conversions
// ---------------------------------------------------------------------------
__global__ void split_rows(const float* __restrict__ in,
                           __half* __restrict__ oh, __half* __restrict__ ol,
                           int rows, int cols, int ldo)
{
    const int c4n = cols / 4;
    const long f = (long)blockIdx.x * blockDim.x + threadIdx.x;
    if (f < (long)rows * c4n) {
        const int row = (int)(f / c4n), c4 = (int)(f % c4n);
        const float4 v = *reinterpret_cast<const float4*>(in + (long)row * cols + c4 * 4);
        __half2 l0, h0 = split_hi(v.x, v.y, l0);
        __half2 l1, h1 = split_hi(v.z, v.w, l1);
        __half2* ph = reinterpret_cast<__half2*>(oh + (long)row * ldo + c4 * 4);
        __half2* pl = reinterpret_cast<__half2*>(ol + (long)row * ldo + c4 * 4);
        ph[0] = h0; ph[1] = h1;
        pl[0] = l0; pl[1] = l1;
    }
}

__global__ void split_transpose(const float* __restrict__ in,
                                __half* __restrict__ oh, __half* __restrict__ ol,
                                int R, int Cc, int ldo, long sIn, long sOut)
{
    __shared__ float t[32][33];
    const int b = blockIdx.z;
    in += (long)b * sIn; oh += (long)b * sOut; ol += (long)b * sOut;
    const int c0 = blockIdx.x * 32, r0 = blockIdx.y * 32;
#pragma unroll
    for (int i = 0; i < 4; i++) {
        const int r = r0 + threadIdx.y + 8 * i, c = c0 + threadIdx.x;
        t[threadIdx.y + 8 * i][threadIdx.x] =
            (r < R && c < Cc) ? in[(long)r * Cc + c] : 0.f;
    }
    __syncthreads();
#pragma unroll
    for (int i = 0; i < 4; i++) {
        const int c = c0 + threadIdx.y + 8 * i, r = r0 + threadIdx.x;
        if (c < Cc && r < R) {
            const float v = t[threadIdx.x][threadIdx.y + 8 * i];
            const __half h = __float2half(v);
            oh[(long)c * ldo + r] = h;
            ol[(long)c * ldo + r] = __float2half(v - __half2float(h));
        }
    }
}

__global__ void conv_H(const float* __restrict__ H,
                       __half* __restrict__ Hh, __half* __restrict__ Hl,
                       __half* __restrict__ HTh, __half* __restrict__ HTl)
{
    __shared__ float t[32][33];
    const int b = blockIdx.z;
    const float* in = H + (long)b * TT * HD;
    const int c0 = blockIdx.x * 32, r0 = blockIdx.y * 32;
#pragma unroll
    for (int i = 0; i < 4; i++) {
        const int r = r0 + threadIdx.y + 8 * i, c = c0 + threadIdx.x;
        float v = 0.f;
        if (r < TT) {
            v = in[(long)r * HD + c];
            const __half h = __float2half(v);
            Hh[(long)b * TT * HD + (long)r * HD + c] = h;
            Hl[(long)b * TT * HD + (long)r * HD + c] =
                __float2half(v - __half2float(h));
        }
        t[threadIdx.y + 8 * i][threadIdx.x] = v;
    }
    __syncthreads();
#pragma unroll
    for (int i = 0; i < 4; i++) {
        const int c = c0 + threadIdx.y + 8 * i, r = r0 + threadIdx.x;
        if (r < TT) {
            const float v = t[threadIdx.x][threadIdx.y + 8 * i];
            const __half h = __float2half(v);
            HTh[(long)b * HD * TTP + (long)c * TTP + r] = h;
            HTl[(long)b * HD * TTP + (long)c * TTP + r] =
                __float2half(v - __half2float(h));
        }
    }
}

// per-row softmax stats only (single pass, online)
__global__ void __launch_bounds__(128) softmax_stats(
    const float* __restrict__ S, float* __restrict__ rmax, float* __restrict__ rinv)
{
    const long row = blockIdx.x;
    const float4* p = reinterpret_cast<const float4*>(S + row * (long)TT);
    const int tid = threadIdx.x;
    float m = -3.0e38f, s = 0.f;
    for (int j = tid; j < TT / 4; j += 128) {
        const float4 v = p[j];
        const float mv = fmaxf(fmaxf(v.x, v.y), fmaxf(v.z, v.w));
        if (mv > m) { s *= __expf(m - mv); m = mv; }
        s += __expf(v.x - m) + __expf(v.y - m) + __expf(v.z - m) + __expf(v.w - m);
    }
#pragma unroll
    for (int o = 16; o; o >>= 1) {
        const float m2 = __shfl_xor_sync(0xffffffffu, m, o);
        const float s2 = __shfl_xor_sync(0xffffffffu, s, o);
        const float M = fmaxf(m, m2);
        s = s * __expf(m - M) + s2 * __expf(m2 - M);
        m = M;
    }
    __shared__ float sm[4], ss[4];
    if ((tid & 31) == 0) { sm[tid >> 5] = m; ss[tid >> 5] = s; }
    __syncthreads();
    if (tid == 0) {
        float M = fmaxf(fmaxf(sm[0], sm[1]), fmaxf(sm[2], sm[3]));
        float S_ = ss[0] * __expf(sm[0] - M) + ss[1] * __expf(sm[1] - M)
                 + ss[2] * __expf(sm[2] - M) + ss[3] * __expf(sm[3] - M);
        rmax[row] = M;
        rinv[row] = 1.0f / S_;
    }
}

// ---------------------------------------------------------------------------
extern "C" void kernel_launch(void* const* d_in, const int* in_sizes, int n_in,
                              void* d_out, int out_size)
{
    const float* X  = (const float*)d_in[0];
    const float* H  = (const float*)d_in[1];
    const float* W1 = (const float*)d_in[2];
    const float* W2 = (const float*)d_in[3];
    float* out = (float*)d_out;

    float *S, *rmax, *rinv;
    cudaGetSymbolAddress((void**)&S, g_S);
    cudaGetSymbolAddress((void**)&rmax, g_rmax);
    cudaGetSymbolAddress((void**)&rinv, g_rinv);
    __half *W2h, *W2l, *XTh, *XTl, *Hh, *Hl, *HTh, *HTl, *W1Th, *W1Tl, *M1h, *M1l, *Gh, *Gl;
    cudaGetSymbolAddress((void**)&W2h, g_W2h);   cudaGetSymbolAddress((void**)&W2l, g_W2l);
    cudaGetSymbolAddress((void**)&XTh, g_XTh);   cudaGetSymbolAddress((void**)&XTl, g_XTl);
    cudaGetSymbolAddress((void**)&Hh,  g_Hh);    cudaGetSymbolAddress((void**)&Hl,  g_Hl);
    cudaGetSymbolAddress((void**)&HTh, g_HTh);   cudaGetSymbolAddress((void**)&HTl, g_HTl);
    cudaGetSymbolAddress((void**)&W1Th, g_W1Th); cudaGetSymbolAddress((void**)&W1Tl, g_W1Tl);
    cudaGetSymbolAddress((void**)&M1h, g_M1h);   cudaGetSymbolAddress((void**)&M1l, g_M1l);
    cudaGetSymbolAddress((void**)&Gh,  g_Gh);    cudaGetSymbolAddress((void**)&Gl,  g_Gl);

    constexpr int SM128 = 2 * (2 * 128 * ROWST + 2 * 128 * ROWST) * 2;   // 81920
    constexpr int SM96  = 2 * (2 * 128 * ROWST + 2 *  96 * ROWST) * 2;   // 71680
    cudaFuncSetAttribute(gemm_h3<128,256,0>, cudaFuncAttributeMaxDynamicSharedMemorySize, SM128);
    cudaFuncSetAttribute(gemm_h3<128,256,2>, cudaFuncAttributeMaxDynamicSharedMemorySize, SM128);
    cudaFuncSetAttribute(gemm_h3< 96,192,1>, cudaFuncAttributeMaxDynamicSharedMemorySize, SM96);
    cudaFuncSetAttribute(gemm_k5_fused, cudaFuncAttributeMaxDynamicSharedMemorySize, SM96);

    const float SCALE = (float)(1.0 / (sqrt((double)XD) * sqrt((double)HD)));

    // conversions
    {
        const long f = (long)CN * (TT / 4);
        split_rows<<<(unsigned)((f + 255) / 256), 256>>>(W2, W2h, W2l, CN, TT, TTP);
    }
    split_transpose<<<dim3(XD / 32, (TT + 31) / 32, BB), dim3(32, 8)>>>(
        X, XTh, XTl, TT, XD, TTP, (long)TT * XD, (long)XD * TTP);
    conv_H<<<dim3(HD / 32, (TT + 31) / 32, BB), dim3(32, 8)>>>(H, Hh, Hl, HTh, HTl);
    split_transpose<<<dim3(HD / 32, (XD + 31) / 32, 1), dim3(32, 8)>>>(
        W1, W1Th, W1Tl, XD, HD, XD, 0L, 0L);

    // K1 (merged): M1[(b,c,x)] = sum_t W2[c,t] * XT[(b,x),t]; scatter fp16
    gemm_h3<128,256,2><<<dim3(48, 3, 1), 256, SM128>>>(
        W2h, W2l, XTh, XTl, nullptr, M1h, M1l,
        CN, BB * XD, TT, TTP, TTP, 0,
        0L, 0L, (long)CN * XD, 1.0f);

    // K2 (merged): G[(b,c)][h] = SCALE * sum_x M1[(b,c),x] * W1T[h,x]; fp16 out
    gemm_h3<96,192,1><<<dim3(2, (BB * CN + 127) / 128, 1), 192, SM96>>>(
        M1h, M1l, W1Th, W1Tl, nullptr, Gh, Gl,
        BB * CN, HD, XD, XD, XD, HD,
        0L, 0L, 0L, SCALE);

    // K3 (batched): S[b] = G[b] @ H[b]^T; fp32 out
    gemm_h3<128,256,0><<<dim3(11, 3, BB), 256, SM128>>>(
        Gh, Gl, Hh, Hl, S, nullptr, nullptr,
        CN, TT, HD, HD, HD, TT,
        (long)CN * HD, (long)TT * HD, (long)CN * TT, 1.0f);

    // K4: softmax stats only
    softmax_stats<<<BB * CN, 128>>>(S, rmax, rinv);

    // K5: fused softmax-apply + GEMM via producer/consumer warps
    gemm_k5_fused<<<dim3(2, 3, BB), 256, SM96>>>(
        S, rmax, rinv, HTh, HTl, out);
}

// round 13
// speedup vs baseline: 1.9216x; 1.9216x over previous
#include <cuda_runtime.h>
#include <cuda_fp16.h>
#include <cstdint>
#include <math.h>

#define BB 64
#define TT 1380
#define TTP 1384
#define XD 96
#define HD 192
#define CN 345

// ---------------- scratch ----------------
static __device__ float g_S [(size_t)BB * CN * TT];
static __device__ __half g_W2h[(size_t)CN * TTP],        g_W2l[(size_t)CN * TTP];
static __device__ __half g_XTh[(size_t)BB * XD * TTP],   g_XTl[(size_t)BB * XD * TTP];
static __device__ __half g_Hh [(size_t)BB * TT * HD],    g_Hl [(size_t)BB * TT * HD];
static __device__ __half g_HTh[(size_t)BB * HD * TTP],   g_HTl[(size_t)BB * HD * TTP];
static __device__ __half g_W1Th[(size_t)HD * XD],        g_W1Tl[(size_t)HD * XD];
static __device__ __half g_M1h[(size_t)BB * CN * XD],    g_M1l[(size_t)BB * CN * XD];
static __device__ __half g_Gh [(size_t)BB * CN * HD],    g_Gl [(size_t)BB * CN * HD];
static __device__ __half g_Ph [(size_t)BB * CN * TTP];

// ---------------- PTX helpers ----------------
__device__ __forceinline__ uint32_t smem_u32(const void* p) {
    uint32_t a;
    asm("{ .reg .u64 t; cvta.to.shared.u64 t, %1; cvt.u32.u64 %0, t; }" : "=r"(a) : "l"(p));
    return a;
}
__device__ __forceinline__ void cpa(uint32_t dst, const void* src, int bytes) {
    asm volatile("cp.async.cg.shared.global [%0], [%1], 16, %2;"
                 :: "r"(dst), "l"(src), "r"(bytes) : "memory");
}
#define CP_COMMIT() asm volatile("cp.async.commit_group;" ::: "memory")
#define CP_WAIT1()  asm volatile("cp.async.wait_group 1;" ::: "memory")
#define CP_WAIT0()  asm volatile("cp.async.wait_group 0;" ::: "memory")

__device__ __forceinline__ void mma16(float* d, const uint32_t* a, uint32_t b0, uint32_t b1) {
    asm volatile(
        "mma.sync.aligned.m16n8k16.row.col.f32.f16.f16.f32 "
        "{%0,%1,%2,%3}, {%4,%5,%6,%7}, {%8,%9}, {%0,%1,%2,%3};"
        : "+f"(d[0]), "+f"(d[1]), "+f"(d[2]), "+f"(d[3])
        : "r"(a[0]), "r"(a[1]), "r"(a[2]), "r"(a[3]), "r"(b0), "r"(b1));
}
__device__ __forceinline__ __half2 split_hi(float x, float y, __half2& lo) {
    const __half hx = __float2half(x), hy = __float2half(y);
    lo = __halves2half2(__float2half(x - __half2float(hx)),
                        __float2half(y - __half2float(hy)));
    return __halves2half2(hx, hy);
}

#define ROWST 40

// ---------------------------------------------------------------------------
// fp16 split GEMM: C[m][n] = alpha * sum_k A[m][k]*B[n][k]
// BM=128, BK=32. BN=128 (NT=256, warps 2x4) or BN=96 (NT=192, warps 2x3).
// ALO=1: A has hi+lo arrays, 3-pass (ah*bh + ah*bl + al*bh)  [bit-identical R11]
// ALO=0: A hi only, 2-pass (ah*bh + ah*bl)                   [for P @ H]
// OUT=0: fp32 to Cf. OUT=1: fp16 hi/lo to Ch/Cl. OUT=2: fp16 scatter by XD.
// ---------------------------------------------------------------------------
template <int BN, int NT, int OUT, int ALO>
__global__ void __launch_bounds__(NT, 2) gemm_h3(
    const __half* __restrict__ Agh, const __half* __restrict__ Agl,
    const __half* __restrict__ Bgh, const __half* __restrict__ Bgl,
    float* __restrict__ Cf, __half* __restrict__ Ch, __half* __restrict__ Cl,
    int M, int N, int K, int lda, int ldb, int ldc,
    long sA, long sB, long sC, float alpha)
{
    constexpr int WCOLS = BN / 32;
    constexpr int ARR_A = 128 * ROWST;
    constexpr int ARR_B = BN * ROWST;
    constexpr int NA = ALO ? 2 : 1;
    constexpr int STG = NA * ARR_A + 2 * ARR_B;

    extern __shared__ __half sm[];
    const uint32_t sb = smem_u32(sm);
    const int tid = threadIdx.x;
    const int wid = tid >> 5, lane = tid & 31;
    const int wm = wid / WCOLS, wn = wid % WCOLS;
    const int grp = lane >> 2, qid = lane & 3;
    const int b = blockIdx.z;

    Agh += (long)b * sA;
    if (ALO) Agl += (long)b * sA;
    Bgh += (long)b * sB; Bgl += (long)b * sB;
    if (OUT == 0) Cf += (long)b * sC;

    const int m0 = blockIdx.y * 128;
    const int n0 = blockIdx.x * BN;

    int mtN = (M - m0 - wm * 64 + 15) >> 4;
    if (mtN < 0) mtN = 0; if (mtN > 4) mtN = 4;
    int ntN = (N - n0 - wn * 32 + 7) >> 3;
    if (ntN < 0) ntN = 0; if (ntN > 4) ntN = 4;

    float acc[4][4][4];
#pragma unroll
    for (int i = 0; i < 4; i++)
#pragma unroll
        for (int j = 0; j < 4; j++)
#pragma unroll
            for (int r = 0; r < 4; r++) acc[i][j][r] = 0.f;

    auto ldst = [&](int kb) {
        const uint32_t base = sb + (uint32_t)(kb & 1) * (STG * 2);
        const int k0 = kb * 32;
        for (int f = tid; f < 128 * 4; f += NT) {
            const int row = f >> 2, ch = f & 3;
            const int gk = k0 + ch * 8;
            int kbytes = (K - gk) * 2;
            if (kbytes > 16) kbytes = 16;
            if (kbytes < 0) kbytes = 0;
            const int gm = m0 + row;
            const int bytes = (gm < M) ? kbytes : 0;
            const long off = bytes ? ((long)gm * lda + gk) : 0;
            const uint32_t doff = (uint32_t)(row * ROWST + ch * 8) * 2;
            cpa(base + doff, Agh + off, bytes);
            if (ALO) cpa(base + ARR_A * 2 + doff, Agl + off, bytes);
        }
        for (int f = tid; f < BN * 4; f += NT) {
            const int row = f >> 2, ch = f & 3;
            const int gk = k0 + ch * 8;
            int kbytes = (K - gk) * 2;
            if (kbytes > 16) kbytes = 16;
            if (kbytes < 0) kbytes = 0;
            const int gn = n0 + row;
            const int bytes = (gn < N) ? kbytes : 0;
            const long off = bytes ? ((long)gn * ldb + gk) : 0;
            const uint32_t doff = (uint32_t)(row * ROWST + ch * 8) * 2;
            cpa(base + NA * ARR_A * 2 + doff, Bgh + off, bytes);
            cpa(base + NA * ARR_A * 2 + ARR_B * 2 + doff, Bgl + off, bytes);
        }
    };

    const int nb = (K + 31) >> 5;
    ldst(0); CP_COMMIT();

    for (int kb = 0; kb < nb; kb++) {
        if (kb + 1 < nb) { ldst(kb + 1); CP_COMMIT(); CP_WAIT1(); }
        else             { CP_WAIT0(); }
        __syncthreads();

        const __half* Ash = sm + (kb & 1) * STG;
        const __half* Asl = Ash + ARR_A;           // valid only if ALO
        const __half* Bsh = Ash + NA * ARR_A;
        const __half* Bsl = Bsh + ARR_B;

#pragma unroll
        for (int kc = 0; kc < 2; kc++) {
            const int kf = kc * 16;
            uint32_t ah[4][4], al[4][4];
#pragma unroll
            for (int mt = 0; mt < 4; mt++) {
                if (mt < mtN) {
                    const int r0 = wm * 64 + mt * 16 + grp;
                    ah[mt][0] = *(const uint32_t*)(Ash + (r0    ) * ROWST + kf     + 2 * qid);
                    ah[mt][1] = *(const uint32_t*)(Ash + (r0 + 8) * ROWST + kf     + 2 * qid);
                    ah[mt][2] = *(const uint32_t*)(Ash + (r0    ) * ROWST + kf + 8 + 2 * qid);
                    ah[mt][3] = *(const uint32_t*)(Ash + (r0 + 8) * ROWST + kf + 8 + 2 * qid);
                    if (ALO) {
                        al[mt][0] = *(const uint32_t*)(Asl + (r0    ) * ROWST + kf     + 2 * qid);
                        al[mt][1] = *(const uint32_t*)(Asl + (r0 + 8) * ROWST + kf     + 2 * qid);
                        al[mt][2] = *(const uint32_t*)(Asl + (r0    ) * ROWST + kf + 8 + 2 * qid);
                        al[mt][3] = *(const uint32_t*)(Asl + (r0 + 8) * ROWST + kf + 8 + 2 * qid);
                    }
                }
            }
#pragma unroll
            for (int nt = 0; nt < 4; nt++) {
                if (nt < ntN) {
                    const int c0 = wn * 32 + nt * 8 + grp;
                    const uint32_t bh0 = *(const uint32_t*)(Bsh + c0 * ROWST + kf     + 2 * qid);
                    const uint32_t bh1 = *(const uint32_t*)(Bsh + c0 * ROWST + kf + 8 + 2 * qid);
                    const uint32_t bl0 = *(const uint32_t*)(Bsl + c0 * ROWST + kf     + 2 * qid);
                    const uint32_t bl1 = *(const uint32_t*)(Bsl + c0 * ROWST + kf + 8 + 2 * qid);
#pragma unroll
                    for (int mt = 0; mt < 4; mt++) {
                        if (mt < mtN) {
                            mma16(acc[mt][nt], ah[mt], bh0, bh1);
                            mma16(acc[mt][nt], ah[mt], bl0, bl1);
                            if (ALO) mma16(acc[mt][nt], al[mt], bh0, bh1);
                        }
                    }
                }
            }
        }
        __syncthreads();
    }

    // ---- epilogue ----
#pragma unroll
    for (int mt = 0; mt < 4; mt++) {
        if (mt >= mtN) break;
#pragma unroll
        for (int nt = 0; nt < 4; nt++) {
            if (nt >= ntN) break;
            const int gmA = m0 + wm * 64 + mt * 16 + grp;
            const int gn  = n0 + wn * 32 + nt * 8 + 2 * qid;
            if (gn + 2 > N) continue;
#pragma unroll
            for (int half_ = 0; half_ < 2; half_++) {
                const int gm = gmA + half_ * 8;
                if (gm >= M) continue;
                const float v0 = acc[mt][nt][half_ * 2 + 0] * alpha;
                const float v1 = acc[mt][nt][half_ * 2 + 1] * alpha;
                if (OUT == 0) {
                    *reinterpret_cast<float2*>(Cf + (long)gm * ldc + gn) =
                        make_float2(v0, v1);
                } else if (OUT == 1) {
                    __half2 lo, hi = split_hi(v0, v1, lo);
                    *reinterpret_cast<__half2*>(Ch + (long)gm * ldc + gn) = hi;
                    *reinterpret_cast<__half2*>(Cl + (long)gm * ldc + gn) = lo;
                } else {
                    const int b1 = gn / XD, x = gn - b1 * XD;
                    const long addr = (long)b1 * sC + (long)gm * XD + x;
                    __half2 lo, hi = split_hi(v0, v1, lo);
                    *reinterpret_cast<__half2*>(Ch + addr) = hi;
                    *reinterpret_cast<__half2*>(Cl + addr) = lo;
                }
            }
        }
    }
}

// ---------------------------------------------------------------------------
// conversions
// ---------------------------------------------------------------------------
__global__ void split_rows(const float* __restrict__ in,
                           __half* __restrict__ oh, __half* __restrict__ ol,
                           int rows, int cols, int ldo)
{
    const int c4n = cols / 4;
    const long f = (long)blockIdx.x * blockDim.x + threadIdx.x;
    if (f < (long)rows * c4n) {
        const int row = (int)(f / c4n), c4 = (int)(f % c4n);
        const float4 v = *reinterpret_cast<const float4*>(in + (long)row * cols + c4 * 4);
        __half2 l0, h0 = split_hi(v.x, v.y, l0);
        __half2 l1, h1 = split_hi(v.z, v.w, l1);
        __half2* ph = reinterpret_cast<__half2*>(oh + (long)row * ldo + c4 * 4);
        __half2* pl = reinterpret_cast<__half2*>(ol + (long)row * ldo + c4 * 4);
        ph[0] = h0; ph[1] = h1;
        pl[0] = l0; pl[1] = l1;
    }
}

__global__ void split_transpose(const float* __restrict__ in,
                                __half* __restrict__ oh, __half* __restrict__ ol,
                                int R, int Cc, int ldo, long sIn, long sOut)
{
    __shared__ float t[32][33];
    const int b = blockIdx.z;
    in += (long)b * sIn; oh += (long)b * sOut; ol += (long)b * sOut;
    const int c0 = blockIdx.x * 32, r0 = blockIdx.y * 32;
#pragma unroll
    for (int i = 0; i < 4; i++) {
        const int r = r0 + threadIdx.y + 8 * i, c = c0 + threadIdx.x;
        t[threadIdx.y + 8 * i][threadIdx.x] =
            (r < R && c < Cc) ? in[(long)r * Cc + c] : 0.f;
    }
    __syncthreads();
#pragma unroll
    for (int i = 0; i < 4; i++) {
        const int c = c0 + threadIdx.y + 8 * i, r = r0 + threadIdx.x;
        if (c < Cc && r < R) {
            const float v = t[threadIdx.x][threadIdx.y + 8 * i];
            const __half h = __float2half(v);
            oh[(long)c * ldo + r] = h;
            ol[(long)c * ldo + r] = __float2half(v - __half2float(h));
        }
    }
}

__global__ void conv_H(const float* __restrict__ H,
                       __half* __restrict__ Hh, __half* __restrict__ Hl,
                       __half* __restrict__ HTh, __half* __restrict__ HTl)
{
    __shared__ float t[32][33];
    const int b = blockIdx.z;
    const float* in = H + (long)b * TT * HD;
    const int c0 = blockIdx.x * 32, r0 = blockIdx.y * 32;
#pragma unroll
    for (int i = 0; i < 4; i++) {
        const int r = r0 + threadIdx.y + 8 * i, c = c0 + threadIdx.x;
        float v = 0.f;
        if (r < TT) {
            v = in[(long)r * HD + c];
            const __half h = __float2half(v);
            Hh[(long)b * TT * HD + (long)r * HD + c] = h;
            Hl[(long)b * TT * HD + (long)r * HD + c] =
                __float2half(v - __half2float(h));
        }
        t[threadIdx.y + 8 * i][threadIdx.x] = v;
    }
    __syncthreads();
#pragma unroll
    for (int i = 0; i < 4; i++) {
        const int c = c0 + threadIdx.y + 8 * i, r = r0 + threadIdx.x;
        if (r < TT) {
            const float v = t[threadIdx.x][threadIdx.y + 8 * i];
            const __half h = __float2half(v);
            HTh[(long)b * HD * TTP + (long)c * TTP + r] = h;
            HTl[(long)b * HD * TTP + (long)c * TTP + r] =
                __float2half(v - __half2float(h));
        }
    }
}

// fused softmax with smem row cache: read S once, write P (fp16 hi only)
__global__ void __launch_bounds__(128) softmax_fused(
    const float* __restrict__ S, __half* __restrict__ oh)
{
    __shared__ float row[TT];
    __shared__ float sm[4], ss[4];
    const long r = blockIdx.x;
    const float4* p = reinterpret_cast<const float4*>(S + r * (long)TT);
    const int tid = threadIdx.x;

    float m = -3.0e38f, s = 0.f;
    for (int j = tid; j < TT / 4; j += 128) {
        const float4 v = p[j];
        *reinterpret_cast<float4*>(&row[j * 4]) = v;
        const float mv = fmaxf(fmaxf(v.x, v.y), fmaxf(v.z, v.w));
        if (mv > m) { s *= __expf(m - mv); m = mv; }
        s += __expf(v.x - m) + __expf(v.y - m) + __expf(v.z - m) + __expf(v.w - m);
    }
#pragma unroll
    for (int o = 16; o; o >>= 1) {
        const float m2 = __shfl_xor_sync(0xffffffffu, m, o);
        const float s2 = __shfl_xor_sync(0xffffffffu, s, o);
        const float M = fmaxf(m, m2);
        s = s * __expf(m - M) + s2 * __expf(m2 - M);
        m = M;
    }
    if ((tid & 31) == 0) { sm[tid >> 5] = m; ss[tid >> 5] = s; }
    __syncthreads();
    const float M = fmaxf(fmaxf(sm[0], sm[1]), fmaxf(sm[2], sm[3]));
    const float S_ = ss[0] * __expf(sm[0] - M) + ss[1] * __expf(sm[1] - M)
                   + ss[2] * __expf(sm[2] - M) + ss[3] * __expf(sm[3] - M);
    const float rv = 1.0f / S_;

    for (int j = tid; j < TT / 4; j += 128) {
        const float4 v = *reinterpret_cast<const float4*>(&row[j * 4]);
        const float f0 = __expf(v.x - M) * rv, f1 = __expf(v.y - M) * rv;
        const float f2 = __expf(v.z - M) * rv, f3 = __expf(v.w - M) * rv;
        __half2* ph = reinterpret_cast<__half2*>(oh + r * (long)TTP + j * 4);
        ph[0] = __halves2half2(__float2half(f0), __float2half(f1));
        ph[1] = __halves2half2(__float2half(f2), __float2half(f3));
    }
}

// ---------------------------------------------------------------------------
extern "C" void kernel_launch(void* const* d_in, const int* in_sizes, int n_in,
                              void* d_out, int out_size)
{
    const float* X  = (const float*)d_in[0];
    const float* H  = (const float*)d_in[1];
    const float* W1 = (const float*)d_in[2];
    const float* W2 = (const float*)d_in[3];
    float* out = (float*)d_out;

    float* S;
    cudaGetSymbolAddress((void**)&S, g_S);
    __half *W2h, *W2l, *XTh, *XTl, *Hh, *Hl, *HTh, *HTl, *W1Th, *W1Tl;
    __half *M1h, *M1l, *Gh, *Gl, *Ph;
    cudaGetSymbolAddress((void**)&W2h, g_W2h);   cudaGetSymbolAddress((void**)&W2l, g_W2l);
    cudaGetSymbolAddress((void**)&XTh, g_XTh);   cudaGetSymbolAddress((void**)&XTl, g_XTl);
    cudaGetSymbolAddress((void**)&Hh,  g_Hh);    cudaGetSymbolAddress((void**)&Hl,  g_Hl);
    cudaGetSymbolAddress((void**)&HTh, g_HTh);   cudaGetSymbolAddress((void**)&HTl, g_HTl);
    cudaGetSymbolAddress((void**)&W1Th, g_W1Th); cudaGetSymbolAddress((void**)&W1Tl, g_W1Tl);
    cudaGetSymbolAddress((void**)&M1h, g_M1h);   cudaGetSymbolAddress((void**)&M1l, g_M1l);
    cudaGetSymbolAddress((void**)&Gh,  g_Gh);    cudaGetSymbolAddress((void**)&Gl,  g_Gl);
    cudaGetSymbolAddress((void**)&Ph,  g_Ph);

    constexpr int SM128  = 2 * (2 * 128 * ROWST + 2 * 128 * ROWST) * 2;   // 81920
    constexpr int SM96   = 2 * (2 * 128 * ROWST + 2 *  96 * ROWST) * 2;   // 71680
    constexpr int SM96A1 = 2 * (1 * 128 * ROWST + 2 *  96 * ROWST) * 2;   // 51200
    cudaFuncSetAttribute(gemm_h3<128,256,0,1>, cudaFuncAttributeMaxDynamicSharedMemorySize, SM128);
    cudaFuncSetAttribute(gemm_h3<128,256,2,1>, cudaFuncAttributeMaxDynamicSharedMemorySize, SM128);
    cudaFuncSetAttribute(gemm_h3< 96,192,1,1>, cudaFuncAttributeMaxDynamicSharedMemorySize, SM96);
    cudaFuncSetAttribute(gemm_h3< 96,192,0,0>, cudaFuncAttributeMaxDynamicSharedMemorySize, SM96A1);

    const float SCALE = (float)(1.0 / (sqrt((double)XD) * sqrt((double)HD)));

    // conversions
    {
        const long f = (long)CN * (TT / 4);
        split_rows<<<(unsigned)((f + 255) / 256), 256>>>(W2, W2h, W2l, CN, TT, TTP);
    }
    split_transpose<<<dim3(XD / 32, (TT + 31) / 32, BB), dim3(32, 8)>>>(
        X, XTh, XTl, TT, XD, TTP, (long)TT * XD, (long)XD * TTP);
    conv_H<<<dim3(HD / 32, (TT + 31) / 32, BB), dim3(32, 8)>>>(H, Hh, Hl, HTh, HTl);
    split_transpose<<<dim3(HD / 32, (XD + 31) / 32, 1), dim3(32, 8)>>>(
        W1, W1Th, W1Tl, XD, HD, XD, 0L, 0L);

    // K1 (merged): M1[(b,c,x)] = sum_t W2[c,t] * XT[(b,x),t]; scatter fp16
    gemm_h3<128,256,2,1><<<dim3(48, 3, 1), 256, SM128>>>(
        W2h, W2l, XTh, XTl, nullptr, M1h, M1l,
        CN, BB * XD, TT, TTP, TTP, 0,
        0L, 0L, (long)CN * XD, 1.0f);

    // K2 (merged): G[(b,c)][h] = SCALE * sum_x M1[(b,c),x] * W1T[h,x]; fp16 out
    gemm_h3<96,192,1,1><<<dim3(2, (BB * CN + 127) / 128, 1), 192, SM96>>>(
        M1h, M1l, W1Th, W1Tl, nullptr, Gh, Gl,
        BB * CN, HD, XD, XD, XD, HD,
        0L, 0L, 0L, SCALE);

    // K3 (batched): S[b] = G[b] @ H[b]^T; fp32 out
    gemm_h3<128,256,0,1><<<dim3(11, 3, BB), 256, SM128>>>(
        Gh, Gl, Hh, Hl, S, nullptr, nullptr,
        CN, TT, HD, HD, HD, TT,
        (long)CN * HD, (long)TT * HD, (long)CN * TT, 1.0f);

    // K4: fused softmax stats + P emit (fp16 hi only, smem row cache)
    softmax_fused<<<BB * CN, 128>>>(S, Ph);

    // K5 (batched): out[b] = P[b] @ H[b]; 2-pass (A hi only), BN=96
    gemm_h3<96,192,0,0><<<dim3(2, 3, BB), 192, SM96A1>>>(
        Ph, nullptr, HTh, HTl, out, nullptr, nullptr,
        CN, HD, TT, TTP, TTP, HD,
        (long)CN * TTP, (long)HD * TTP, (long)CN * HD, 1.0f);
}

// round 15
// speedup vs baseline: 2.0905x; 1.0879x over previous
#include <cuda_runtime.h>
#include <cuda_fp16.h>
#include <cstdint>
#include <math.h>

#define BB 64
#define TT 1380
#define TTP 1384
#define XD 96
#define HD 192
#define CN 345

// ---------------- scratch ----------------
static __device__ float g_S [(size_t)BB * CN * TT];
static __device__ __half g_W2h[(size_t)CN * TTP],        g_W2l[(size_t)CN * TTP];
static __device__ __half g_XTh[(size_t)BB * XD * TTP],   g_XTl[(size_t)BB * XD * TTP];
static __device__ __half g_Hh [(size_t)BB * TT * HD],    g_Hl [(size_t)BB * TT * HD];
static __device__ __half g_HTh[(size_t)BB * HD * TTP],   g_HTl[(size_t)BB * HD * TTP];
static __device__ __half g_W1Th[(size_t)HD * XD],        g_W1Tl[(size_t)HD * XD];
static __device__ __half g_M1h[(size_t)BB * CN * XD],    g_M1l[(size_t)BB * CN * XD];
static __device__ __half g_Gh [(size_t)BB * CN * HD],    g_Gl [(size_t)BB * CN * HD];
static __device__ __half g_Ph [(size_t)BB * CN * TTP];

// ---------------- PTX helpers ----------------
__device__ __forceinline__ uint32_t smem_u32(const void* p) {
    uint32_t a;
    asm("{ .reg .u64 t; cvta.to.shared.u64 t, %1; cvt.u32.u64 %0, t; }" : "=r"(a) : "l"(p));
    return a;
}
__device__ __forceinline__ void cpa(uint32_t dst, const void* src, int bytes) {
    asm volatile("cp.async.cg.shared.global [%0], [%1], 16, %2;"
                 :: "r"(dst), "l"(src), "r"(bytes) : "memory");
}
#define CP_COMMIT() asm volatile("cp.async.commit_group;" ::: "memory")
#define CP_WAIT1()  asm volatile("cp.async.wait_group 1;" ::: "memory")
#define CP_WAIT0()  asm volatile("cp.async.wait_group 0;" ::: "memory")

__device__ __forceinline__ void mma16(float* d, const uint32_t* a, uint32_t b0, uint32_t b1) {
    asm volatile(
        "mma.sync.aligned.m16n8k16.row.col.f32.f16.f16.f32 "
        "{%0,%1,%2,%3}, {%4,%5,%6,%7}, {%8,%9}, {%0,%1,%2,%3};"
        : "+f"(d[0]), "+f"(d[1]), "+f"(d[2]), "+f"(d[3])
        : "r"(a[0]), "r"(a[1]), "r"(a[2]), "r"(a[3]), "r"(b0), "r"(b1));
}
__device__ __forceinline__ __half2 split_hi(float x, float y, __half2& lo) {
    const __half hx = __float2half(x), hy = __float2half(y);
    lo = __halves2half2(__float2half(x - __half2float(hx)),
                        __float2half(y - __half2float(hy)));
    return __halves2half2(hx, hy);
}

#define ROWST 40

// ---------------------------------------------------------------------------
// fp16 split GEMM: C[m][n] = alpha * sum_k A[m][k]*B[n][k]
// BM=128, BK=32. BN=128 (NT=256, warps 2x4) or BN=96 (NT=192, warps 2x3).
// ALO: A lo array present. BLO: B lo array present.
//   (1,1): 3-pass ah*bh + ah*bl + al*bh   [logits chain, bit-identical R13]
//   (0,1): 2-pass ah*bh + ah*bl
//   (0,0): 1-pass ah*bh                   [P @ H]
// OUT=0: fp32 to Cf. OUT=1: fp16 hi/lo to Ch/Cl. OUT=2: fp16 scatter by XD.
// ---------------------------------------------------------------------------
template <int BN, int NT, int OUT, int ALO, int BLO>
__global__ void __launch_bounds__(NT, 2) gemm_h3(
    const __half* __restrict__ Agh, const __half* __restrict__ Agl,
    const __half* __restrict__ Bgh, const __half* __restrict__ Bgl,
    float* __restrict__ Cf, __half* __restrict__ Ch, __half* __restrict__ Cl,
    int M, int N, int K, int lda, int ldb, int ldc,
    long sA, long sB, long sC, float alpha)
{
    constexpr int WCOLS = BN / 32;
    constexpr int ARR_A = 128 * ROWST;
    constexpr int ARR_B = BN * ROWST;
    constexpr int NA = ALO ? 2 : 1;
    constexpr int NB = BLO ? 2 : 1;
    constexpr int STG = NA * ARR_A + NB * ARR_B;

    extern __shared__ __half sm[];
    const uint32_t sb = smem_u32(sm);
    const int tid = threadIdx.x;
    const int wid = tid >> 5, lane = tid & 31;
    const int wm = wid / WCOLS, wn = wid % WCOLS;
    const int grp = lane >> 2, qid = lane & 3;
    const int b = blockIdx.z;

    Agh += (long)b * sA;
    if (ALO) Agl += (long)b * sA;
    Bgh += (long)b * sB;
    if (BLO) Bgl += (long)b * sB;
    if (OUT == 0) Cf += (long)b * sC;

    const int m0 = blockIdx.y * 128;
    const int n0 = blockIdx.x * BN;

    int mtN = (M - m0 - wm * 64 + 15) >> 4;
    if (mtN < 0) mtN = 0; if (mtN > 4) mtN = 4;
    int ntN = (N - n0 - wn * 32 + 7) >> 3;
    if (ntN < 0) ntN = 0; if (ntN > 4) ntN = 4;

    float acc[4][4][4];
#pragma unroll
    for (int i = 0; i < 4; i++)
#pragma unroll
        for (int j = 0; j < 4; j++)
#pragma unroll
            for (int r = 0; r < 4; r++) acc[i][j][r] = 0.f;

    auto ldst = [&](int kb) {
        const uint32_t base = sb + (uint32_t)(kb & 1) * (STG * 2);
        const int k0 = kb * 32;
        for (int f = tid; f < 128 * 4; f += NT) {
            const int row = f >> 2, ch = f & 3;
            const int gk = k0 + ch * 8;
            int kbytes = (K - gk) * 2;
            if (kbytes > 16) kbytes = 16;
            if (kbytes < 0) kbytes = 0;
            const int gm = m0 + row;
            const int bytes = (gm < M) ? kbytes : 0;
            const long off = bytes ? ((long)gm * lda + gk) : 0;
            const uint32_t doff = (uint32_t)(row * ROWST + ch * 8) * 2;
            cpa(base + doff, Agh + off, bytes);
            if (ALO) cpa(base + ARR_A * 2 + doff, Agl + off, bytes);
        }
        for (int f = tid; f < BN * 4; f += NT) {
            const int row = f >> 2, ch = f & 3;
            const int gk = k0 + ch * 8;
            int kbytes = (K - gk) * 2;
            if (kbytes > 16) kbytes = 16;
            if (kbytes < 0) kbytes = 0;
            const int gn = n0 + row;
            const int bytes = (gn < N) ? kbytes : 0;
            const long off = bytes ? ((long)gn * ldb + gk) : 0;
            const uint32_t doff = (uint32_t)(row * ROWST + ch * 8) * 2;
            cpa(base + NA * ARR_A * 2 + doff, Bgh + off, bytes);
            if (BLO) cpa(base + NA * ARR_A * 2 + ARR_B * 2 + doff, Bgl + off, bytes);
        }
    };

    const int nb = (K + 31) >> 5;
    ldst(0); CP_COMMIT();

    for (int kb = 0; kb < nb; kb++) {
        if (kb + 1 < nb) { ldst(kb + 1); CP_COMMIT(); CP_WAIT1(); }
        else             { CP_WAIT0(); }
        __syncthreads();

        const __half* Ash = sm + (kb & 1) * STG;
        const __half* Asl = Ash + ARR_A;           // valid only if ALO
        const __half* Bsh = Ash + NA * ARR_A;
        const __half* Bsl = Bsh + ARR_B;           // valid only if BLO

#pragma unroll
        for (int kc = 0; kc < 2; kc++) {
            const int kf = kc * 16;
            uint32_t ah[4][4], al[4][4];
#pragma unroll
            for (int mt = 0; mt < 4; mt++) {
                if (mt < mtN) {
                    const int r0 = wm * 64 + mt * 16 + grp;
                    ah[mt][0] = *(const uint32_t*)(Ash + (r0    ) * ROWST + kf     + 2 * qid);
                    ah[mt][1] = *(const uint32_t*)(Ash + (r0 + 8) * ROWST + kf     + 2 * qid);
                    ah[mt][2] = *(const uint32_t*)(Ash + (r0    ) * ROWST + kf + 8 + 2 * qid);
                    ah[mt][3] = *(const uint32_t*)(Ash + (r0 + 8) * ROWST + kf + 8 + 2 * qid);
                    if (ALO) {
                        al[mt][0] = *(const uint32_t*)(Asl + (r0    ) * ROWST + kf     + 2 * qid);
                        al[mt][1] = *(const uint32_t*)(Asl + (r0 + 8) * ROWST + kf     + 2 * qid);
                        al[mt][2] = *(const uint32_t*)(Asl + (r0    ) * ROWST + kf + 8 + 2 * qid);
                        al[mt][3] = *(const uint32_t*)(Asl + (r0 + 8) * ROWST + kf + 8 + 2 * qid);
                    }
                }
            }
#pragma unroll
            for (int nt = 0; nt < 4; nt++) {
                if (nt < ntN) {
                    const int c0 = wn * 32 + nt * 8 + grp;
                    const uint32_t bh0 = *(const uint32_t*)(Bsh + c0 * ROWST + kf     + 2 * qid);
                    const uint32_t bh1 = *(const uint32_t*)(Bsh + c0 * ROWST + kf + 8 + 2 * qid);
                    uint32_t bl0 = 0, bl1 = 0;
                    if (BLO) {
                        bl0 = *(const uint32_t*)(Bsl + c0 * ROWST + kf     + 2 * qid);
                        bl1 = *(const uint32_t*)(Bsl + c0 * ROWST + kf + 8 + 2 * qid);
                    }
#pragma unroll
                    for (int mt = 0; mt < 4; mt++) {
                        if (mt < mtN) {
                            mma16(acc[mt][nt], ah[mt], bh0, bh1);
                            if (BLO) mma16(acc[mt][nt], ah[mt], bl0, bl1);
                            if (ALO) mma16(acc[mt][nt], al[mt], bh0, bh1);
                        }
                    }
                }
            }
        }
        __syncthreads();
    }

    // ---- epilogue ----
#pragma unroll
    for (int mt = 0; mt < 4; mt++) {
        if (mt >= mtN) break;
#pragma unroll
        for (int nt = 0; nt < 4; nt++) {
            if (nt >= ntN) break;
            const int gmA = m0 + wm * 64 + mt * 16 + grp;
            const int gn  = n0 + wn * 32 + nt * 8 + 2 * qid;
            if (gn + 2 > N) continue;
#pragma unroll
            for (int half_ = 0; half_ < 2; half_++) {
                const int gm = gmA + half_ * 8;
                if (gm >= M) continue;
                const float v0 = acc[mt][nt][half_ * 2 + 0] * alpha;
                const float v1 = acc[mt][nt][half_ * 2 + 1] * alpha;
                if (OUT == 0) {
                    *reinterpret_cast<float2*>(Cf + (long)gm * ldc + gn) =
                        make_float2(v0, v1);
                } else if (OUT == 1) {
                    __half2 lo, hi = split_hi(v0, v1, lo);
                    *reinterpret_cast<__half2*>(Ch + (long)gm * ldc + gn) = hi;
                    *reinterpret_cast<__half2*>(Cl + (long)gm * ldc + gn) = lo;
                } else {
                    const int b1 = gn / XD, x = gn - b1 * XD;
                    const long addr = (long)b1 * sC + (long)gm * XD + x;
                    __half2 lo, hi = split_hi(v0, v1, lo);
                    *reinterpret_cast<__half2*>(Ch + addr) = hi;
                    *reinterpret_cast<__half2*>(Cl + addr) = lo;
                }
            }
        }
    }
}

// ---------------------------------------------------------------------------
// conversions
// ---------------------------------------------------------------------------
__global__ void split_rows(const float* __restrict__ in,
                           __half* __restrict__ oh, __half* __restrict__ ol,
                           int rows, int cols, int ldo)
{
    const int c4n = cols / 4;
    const long f = (long)blockIdx.x * blockDim.x + threadIdx.x;
    if (f < (long)rows * c4n) {
        const int row = (int)(f / c4n), c4 = (int)(f % c4n);
        const float4 v = *reinterpret_cast<const float4*>(in + (long)row * cols + c4 * 4);
        __half2 l0, h0 = split_hi(v.x, v.y, l0);
        __half2 l1, h1 = split_hi(v.z, v.w, l1);
        __half2* ph = reinterpret_cast<__half2*>(oh + (long)row * ldo + c4 * 4);
        __half2* pl = reinterpret_cast<__half2*>(ol + (long)row * ldo + c4 * 4);
        ph[0] = h0; ph[1] = h1;
        pl[0] = l0; pl[1] = l1;
    }
}

__global__ void split_transpose(const float* __restrict__ in,
                                __half* __restrict__ oh, __half* __restrict__ ol,
                                int R, int Cc, int ldo, long sIn, long sOut)
{
    __shared__ float t[32][33];
    const int b = blockIdx.z;
    in += (long)b * sIn; oh += (long)b * sOut; ol += (long)b * sOut;
    const int c0 = blockIdx.x * 32, r0 = blockIdx.y * 32;
#pragma unroll
    for (int i = 0; i < 4; i++) {
        const int r = r0 + threadIdx.y + 8 * i, c = c0 + threadIdx.x;
        t[threadIdx.y + 8 * i][threadIdx.x] =
            (r < R && c < Cc) ? in[(long)r * Cc + c] : 0.f;
    }
    __syncthreads();
#pragma unroll
    for (int i = 0; i < 4; i++) {
        const int c = c0 + threadIdx.y + 8 * i, r = r0 + threadIdx.x;
        if (c < Cc && r < R) {
            const float v = t[threadIdx.x][threadIdx.y + 8 * i];
            const __half h = __float2half(v);
            oh[(long)c * ldo + r] = h;
            ol[(long)c * ldo + r] = __float2half(v - __half2float(h));
        }
    }
}

__global__ void conv_H(const float* __restrict__ H,
                       __half* __restrict__ Hh, __half* __restrict__ Hl,
                       __half* __restrict__ HTh, __half* __restrict__ HTl)
{
    __shared__ float t[32][33];
    const int b = blockIdx.z;
    const float* in = H + (long)b * TT * HD;
    const int c0 = blockIdx.x * 32, r0 = blockIdx.y * 32;
#pragma unroll
    for (int i = 0; i < 4; i++) {
        const int r = r0 + threadIdx.y + 8 * i, c = c0 + threadIdx.x;
        float v = 0.f;
        if (r < TT) {
            v = in[(long)r * HD + c];
            const __half h = __float2half(v);
            Hh[(long)b * TT * HD + (long)r * HD + c] = h;
            Hl[(long)b * TT * HD + (long)r * HD + c] =
                __float2half(v - __half2float(h));
        }
        t[threadIdx.y + 8 * i][threadIdx.x] = v;
    }
    __syncthreads();
#pragma unroll
    for (int i = 0; i < 4; i++) {
        const int c = c0 + threadIdx.y + 8 * i, r = r0 + threadIdx.x;
        if (r < TT) {
            const float v = t[threadIdx.x][threadIdx.y + 8 * i];
            const __half h = __float2half(v);
            HTh[(long)b * HD * TTP + (long)c * TTP + r] = h;
            HTl[(long)b * HD * TTP + (long)c * TTP + r] =
                __float2half(v - __half2float(h));
        }
    }
}

// fused softmax with smem row cache: read S once, write P (fp16 hi only)
__global__ void __launch_bounds__(128) softmax_fused(
    const float* __restrict__ S, __half* __restrict__ oh)
{
    __shared__ float row[TT];
    __shared__ float sm[4], ss[4];
    const long r = blockIdx.x;
    const float4* p = reinterpret_cast<const float4*>(S + r * (long)TT);
    const int tid = threadIdx.x;

    float m = -3.0e38f, s = 0.f;
    for (int j = tid; j < TT / 4; j += 128) {
        const float4 v = p[j];
        *reinterpret_cast<float4*>(&row[j * 4]) = v;
        const float mv = fmaxf(fmaxf(v.x, v.y), fmaxf(v.z, v.w));
        if (mv > m) { s *= __expf(m - mv); m = mv; }
        s += __expf(v.x - m) + __expf(v.y - m) + __expf(v.z - m) + __expf(v.w - m);
    }
#pragma unroll
    for (int o = 16; o; o >>= 1) {
        const float m2 = __shfl_xor_sync(0xffffffffu, m, o);
        const float s2 = __shfl_xor_sync(0xffffffffu, s, o);
        const float M = fmaxf(m, m2);
        s = s * __expf(m - M) + s2 * __expf(m2 - M);
        m = M;
    }
    if ((tid & 31) == 0) { sm[tid >> 5] = m; ss[tid >> 5] = s; }
    __syncthreads();
    const float M = fmaxf(fmaxf(sm[0], sm[1]), fmaxf(sm[2], sm[3]));
    const float S_ = ss[0] * __expf(sm[0] - M) + ss[1] * __expf(sm[1] - M)
                   + ss[2] * __expf(sm[2] - M) + ss[3] * __expf(sm[3] - M);
    const float rv = 1.0f / S_;

    for (int j = tid; j < TT / 4; j += 128) {
        const float4 v = *reinterpret_cast<const float4*>(&row[j * 4]);
        const float f0 = __expf(v.x - M) * rv, f1 = __expf(v.y - M) * rv;
        const float f2 = __expf(v.z - M) * rv, f3 = __expf(v.w - M) * rv;
        __half2* ph = reinterpret_cast<__half2*>(oh + r * (long)TTP + j * 4);
        ph[0] = __halves2half2(__float2half(f0), __float2half(f1));
        ph[1] = __halves2half2(__float2half(f2), __float2half(f3));
    }
}

// ---------------------------------------------------------------------------
extern "C" void kernel_launch(void* const* d_in, const int* in_sizes, int n_in,
                              void* d_out, int out_size)
{
    const float* X  = (const float*)d_in[0];
    const float* H  = (const float*)d_in[1];
    const float* W1 = (const float*)d_in[2];
    const float* W2 = (const float*)d_in[3];
    float* out = (float*)d_out;

    float* S;
    cudaGetSymbolAddress((void**)&S, g_S);
    __half *W2h, *W2l, *XTh, *XTl, *Hh, *Hl, *HTh, *HTl, *W1Th, *W1Tl;
    __half *M1h, *M1l, *Gh, *Gl, *Ph;
    cudaGetSymbolAddress((void**)&W2h, g_W2h);   cudaGetSymbolAddress((void**)&W2l, g_W2l);
    cudaGetSymbolAddress((void**)&XTh, g_XTh);   cudaGetSymbolAddress((void**)&XTl, g_XTl);
    cudaGetSymbolAddress((void**)&Hh,  g_Hh);    cudaGetSymbolAddress((void**)&Hl,  g_Hl);
    cudaGetSymbolAddress((void**)&HTh, g_HTh);   cudaGetSymbolAddress((void**)&HTl, g_HTl);
    cudaGetSymbolAddress((void**)&W1Th, g_W1Th); cudaGetSymbolAddress((void**)&W1Tl, g_W1Tl);
    cudaGetSymbolAddress((void**)&M1h, g_M1h);   cudaGetSymbolAddress((void**)&M1l, g_M1l);
    cudaGetSymbolAddress((void**)&Gh,  g_Gh);    cudaGetSymbolAddress((void**)&Gl,  g_Gl);
    cudaGetSymbolAddress((void**)&Ph,  g_Ph);

    constexpr int SM128   = 2 * (2 * 128 * ROWST + 2 * 128 * ROWST) * 2;   // 81920
    constexpr int SM96    = 2 * (2 * 128 * ROWST + 2 *  96 * ROWST) * 2;   // 71680
    constexpr int SM96A1B1= 2 * (1 * 128 * ROWST + 1 *  96 * ROWST) * 2;   // 35840
    cudaFuncSetAttribute(gemm_h3<128,256,0,1,1>, cudaFuncAttributeMaxDynamicSharedMemorySize, SM128);
    cudaFuncSetAttribute(gemm_h3<128,256,2,1,1>, cudaFuncAttributeMaxDynamicSharedMemorySize, SM128);
    cudaFuncSetAttribute(gemm_h3< 96,192,1,1,1>, cudaFuncAttributeMaxDynamicSharedMemorySize, SM96);
    cudaFuncSetAttribute(gemm_h3< 96,192,0,0,0>, cudaFuncAttributeMaxDynamicSharedMemorySize, SM96A1B1);

    const float SCALE = (float)(1.0 / (sqrt((double)XD) * sqrt((double)HD)));

    // conversions
    {
        const long f = (long)CN * (TT / 4);
        split_rows<<<(unsigned)((f + 255) / 256), 256>>>(W2, W2h, W2l, CN, TT, TTP);
    }
    split_transpose<<<dim3(XD / 32, (TT + 31) / 32, BB), dim3(32, 8)>>>(
        X, XTh, XTl, TT, XD, TTP, (long)TT * XD, (long)XD * TTP);
    conv_H<<<dim3(HD / 32, (TT + 31) / 32, BB), dim3(32, 8)>>>(H, Hh, Hl, HTh, HTl);
    split_transpose<<<dim3(HD / 32, (XD + 31) / 32, 1), dim3(32, 8)>>>(
        W1, W1Th, W1Tl, XD, HD, XD, 0L, 0L);

    // K1 (merged): M1[(b,c,x)] = sum_t W2[c,t] * XT[(b,x),t]; scatter fp16
    gemm_h3<128,256,2,1,1><<<dim3(48, 3, 1), 256, SM128>>>(
        W2h, W2l, XTh, XTl, nullptr, M1h, M1l,
        CN, BB * XD, TT, TTP, TTP, 0,
        0L, 0L, (long)CN * XD, 1.0f);

    // K2 (merged): G[(b,c)][h] = SCALE * sum_x M1[(b,c),x] * W1T[h,x]; fp16 out
    gemm_h3<96,192,1,1,1><<<dim3(2, (BB * CN + 127) / 128, 1), 192, SM96>>>(
        M1h, M1l, W1Th, W1Tl, nullptr, Gh, Gl,
        BB * CN, HD, XD, XD, XD, HD,
        0L, 0L, 0L, SCALE);

    // K3 (batched): S[b] = G[b] @ H[b]^T; fp32 out
    gemm_h3<128,256,0,1,1><<<dim3(11, 3, BB), 256, SM128>>>(
        Gh, Gl, Hh, Hl, S, nullptr, nullptr,
        CN, TT, HD, HD, HD, TT,
        (long)CN * HD, (long)TT * HD, (long)CN * TT, 1.0f);

    // K4: fused softmax stats + P emit (fp16 hi only, smem row cache)
    softmax_fused<<<BB * CN, 128>>>(S, Ph);

    // K5 (batched): out[b] = P[b] @ H[b]; pure fp16 1-pass, BN=96
    gemm_h3<96,192,0,0,0><<<dim3(2, 3, BB), 192, SM96A1B1>>>(
        Ph, nullptr, HTh, nullptr, out, nullptr, nullptr,
        CN, HD, TT, TTP, TTP, HD,
        (long)CN * TTP, (long)HD * TTP, (long)CN * HD, 1.0f);
}

// round 16
// speedup vs baseline: 2.1383x; 1.0228x over previous
#include <cuda_runtime.h>
#include <cuda_fp16.h>
#include <cstdint>
#include <math.h>

#define BB 64
#define TT 1380
#define TTP 1384
#define XD 96
#define HD 192
#define CN 345

// ---------------- scratch ----------------
static __device__ float g_S [(size_t)BB * CN * TT];
static __device__ __half g_W2h[(size_t)CN * TTP],        g_W2l[(size_t)CN * TTP];
static __device__ __half g_XTh[(size_t)BB * XD * TTP],   g_XTl[(size_t)BB * XD * TTP];
static __device__ __half g_Hh [(size_t)BB * TT * HD],    g_Hl [(size_t)BB * TT * HD];
static __device__ __half g_HTh[(size_t)BB * HD * TTP],   g_HTl[(size_t)BB * HD * TTP];
static __device__ __half g_W1Th[(size_t)HD * XD],        g_W1Tl[(size_t)HD * XD];
static __device__ __half g_M1h[(size_t)BB * CN * XD],    g_M1l[(size_t)BB * CN * XD];
static __device__ __half g_Gh [(size_t)BB * CN * HD],    g_Gl [(size_t)BB * CN * HD];
static __device__ __half g_Ph [(size_t)BB * CN * TTP];

// ---------------- PTX helpers ----------------
__device__ __forceinline__ uint32_t smem_u32(const void* p) {
    uint32_t a;
    asm("{ .reg .u64 t; cvta.to.shared.u64 t, %1; cvt.u32.u64 %0, t; }" : "=r"(a) : "l"(p));
    return a;
}
__device__ __forceinline__ void cpa(uint32_t dst, const void* src, int bytes) {
    asm volatile("cp.async.cg.shared.global [%0], [%1], 16, %2;"
                 :: "r"(dst), "l"(src), "r"(bytes) : "memory");
}
#define CP_COMMIT() asm volatile("cp.async.commit_group;" ::: "memory")
#define CP_WAIT1()  asm volatile("cp.async.wait_group 1;" ::: "memory")
#define CP_WAIT0()  asm volatile("cp.async.wait_group 0;" ::: "memory")

__device__ __forceinline__ void mma16(float* d, const uint32_t* a, uint32_t b0, uint32_t b1) {
    asm volatile(
        "mma.sync.aligned.m16n8k16.row.col.f32.f16.f16.f32 "
        "{%0,%1,%2,%3}, {%4,%5,%6,%7}, {%8,%9}, {%0,%1,%2,%3};"
        : "+f"(d[0]), "+f"(d[1]), "+f"(d[2]), "+f"(d[3])
        : "r"(a[0]), "r"(a[1]), "r"(a[2]), "r"(a[3]), "r"(b0), "r"(b1));
}
__device__ __forceinline__ __half2 split_hi(float x, float y, __half2& lo) {
    const __half hx = __float2half(x), hy = __float2half(y);
    lo = __halves2half2(__float2half(x - __half2float(hx)),
                        __float2half(y - __half2float(hy)));
    return __halves2half2(hx, hy);
}

#define ROWST 40

// ---------------------------------------------------------------------------
// fp16 split GEMM: C[m][n] = alpha * sum_k A[m][k]*B[n][k]
// BM=128, BK=32. BN=128 (NT=256, warps 2x4) or BN=96 (NT=192, warps 2x3).
// ALO: A lo array present. BLO: B lo array present. OCC: min blocks/SM.
//   (1,1): 3-pass ah*bh + ah*bl + al*bh   [logits chain]
//   (0,0): 1-pass ah*bh                   [P @ H]
// OUT=0: fp32 to Cf. OUT=1: fp16 hi/lo to Ch/Cl. OUT=2: fp16 scatter by XD.
// ---------------------------------------------------------------------------
template <int BN, int NT, int OUT, int ALO, int BLO, int OCC>
__global__ void __launch_bounds__(NT, OCC) gemm_h3(
    const __half* __restrict__ Agh, const __half* __restrict__ Agl,
    const __half* __restrict__ Bgh, const __half* __restrict__ Bgl,
    float* __restrict__ Cf, __half* __restrict__ Ch, __half* __restrict__ Cl,
    int M, int N, int K, int lda, int ldb, int ldc,
    long sA, long sB, long sC, float alpha)
{
    constexpr int WCOLS = BN / 32;
    constexpr int ARR_A = 128 * ROWST;
    constexpr int ARR_B = BN * ROWST;
    constexpr int NA = ALO ? 2 : 1;
    constexpr int NB = BLO ? 2 : 1;
    constexpr int STG = NA * ARR_A + NB * ARR_B;

    extern __shared__ __half sm[];
    const uint32_t sb = smem_u32(sm);
    const int tid = threadIdx.x;
    const int wid = tid >> 5, lane = tid & 31;
    const int wm = wid / WCOLS, wn = wid % WCOLS;
    const int grp = lane >> 2, qid = lane & 3;
    const int b = blockIdx.z;

    Agh += (long)b * sA;
    if (ALO) Agl += (long)b * sA;
    Bgh += (long)b * sB;
    if (BLO) Bgl += (long)b * sB;
    if (OUT == 0) Cf += (long)b * sC;

    const int m0 = blockIdx.y * 128;
    const int n0 = blockIdx.x * BN;

    int mtN = (M - m0 - wm * 64 + 15) >> 4;
    if (mtN < 0) mtN = 0; if (mtN > 4) mtN = 4;
    int ntN = (N - n0 - wn * 32 + 7) >> 3;
    if (ntN < 0) ntN = 0; if (ntN > 4) ntN = 4;

    float acc[4][4][4];
#pragma unroll
    for (int i = 0; i < 4; i++)
#pragma unroll
        for (int j = 0; j < 4; j++)
#pragma unroll
            for (int r = 0; r < 4; r++) acc[i][j][r] = 0.f;

    auto ldst = [&](int kb) {
        const uint32_t base = sb + (uint32_t)(kb & 1) * (STG * 2);
        const int k0 = kb * 32;
        for (int f = tid; f < 128 * 4; f += NT) {
            const int row = f >> 2, ch = f & 3;
            const int gk = k0 + ch * 8;
            int kbytes = (K - gk) * 2;
            if (kbytes > 16) kbytes = 16;
            if (kbytes < 0) kbytes = 0;
            const int gm = m0 + row;
            const int bytes = (gm < M) ? kbytes : 0;
            const long off = bytes ? ((long)gm * lda + gk) : 0;
            const uint32_t doff = (uint32_t)(row * ROWST + ch * 8) * 2;
            cpa(base + doff, Agh + off, bytes);
            if (ALO) cpa(base + ARR_A * 2 + doff, Agl + off, bytes);
        }
        for (int f = tid; f < BN * 4; f += NT) {
            const int row = f >> 2, ch = f & 3;
            const int gk = k0 + ch * 8;
            int kbytes = (K - gk) * 2;
            if (kbytes > 16) kbytes = 16;
            if (kbytes < 0) kbytes = 0;
            const int gn = n0 + row;
            const int bytes = (gn < N) ? kbytes : 0;
            const long off = bytes ? ((long)gn * ldb + gk) : 0;
            const uint32_t doff = (uint32_t)(row * ROWST + ch * 8) * 2;
            cpa(base + NA * ARR_A * 2 + doff, Bgh + off, bytes);
            if (BLO) cpa(base + NA * ARR_A * 2 + ARR_B * 2 + doff, Bgl + off, bytes);
        }
    };

    const int nb = (K + 31) >> 5;
    ldst(0); CP_COMMIT();

    for (int kb = 0; kb < nb; kb++) {
        if (kb + 1 < nb) { ldst(kb + 1); CP_COMMIT(); CP_WAIT1(); }
        else             { CP_WAIT0(); }
        __syncthreads();

        const __half* Ash = sm + (kb & 1) * STG;
        const __half* Asl = Ash + ARR_A;           // valid only if ALO
        const __half* Bsh = Ash + NA * ARR_A;
        const __half* Bsl = Bsh + ARR_B;           // valid only if BLO

#pragma unroll
        for (int kc = 0; kc < 2; kc++) {
            const int kf = kc * 16;
            uint32_t ah[4][4], al[4][4];
#pragma unroll
            for (int mt = 0; mt < 4; mt++) {
                if (mt < mtN) {
                    const int r0 = wm * 64 + mt * 16 + grp;
                    ah[mt][0] = *(const uint32_t*)(Ash + (r0    ) * ROWST + kf     + 2 * qid);
                    ah[mt][1] = *(const uint32_t*)(Ash + (r0 + 8) * ROWST + kf     + 2 * qid);
                    ah[mt][2] = *(const uint32_t*)(Ash + (r0    ) * ROWST + kf + 8 + 2 * qid);
                    ah[mt][3] = *(const uint32_t*)(Ash + (r0 + 8) * ROWST + kf + 8 + 2 * qid);
                    if (ALO) {
                        al[mt][0] = *(const uint32_t*)(Asl + (r0    ) * ROWST + kf     + 2 * qid);
                        al[mt][1] = *(const uint32_t*)(Asl + (r0 + 8) * ROWST + kf     + 2 * qid);
                        al[mt][2] = *(const uint32_t*)(Asl + (r0    ) * ROWST + kf + 8 + 2 * qid);
                        al[mt][3] = *(const uint32_t*)(Asl + (r0 + 8) * ROWST + kf + 8 + 2 * qid);
                    }
                }
            }
#pragma unroll
            for (int nt = 0; nt < 4; nt++) {
                if (nt < ntN) {
                    const int c0 = wn * 32 + nt * 8 + grp;
                    const uint32_t bh0 = *(const uint32_t*)(Bsh + c0 * ROWST + kf     + 2 * qid);
                    const uint32_t bh1 = *(const uint32_t*)(Bsh + c0 * ROWST + kf + 8 + 2 * qid);
                    uint32_t bl0 = 0, bl1 = 0;
                    if (BLO) {
                        bl0 = *(const uint32_t*)(Bsl + c0 * ROWST + kf     + 2 * qid);
                        bl1 = *(const uint32_t*)(Bsl + c0 * ROWST + kf + 8 + 2 * qid);
                    }
#pragma unroll
                    for (int mt = 0; mt < 4; mt++) {
                        if (mt < mtN) {
                            mma16(acc[mt][nt], ah[mt], bh0, bh1);
                            if (BLO) mma16(acc[mt][nt], ah[mt], bl0, bl1);
                            if (ALO) mma16(acc[mt][nt], al[mt], bh0, bh1);
                        }
                    }
                }
            }
        }
        __syncthreads();
    }

    // ---- epilogue ----
#pragma unroll
    for (int mt = 0; mt < 4; mt++) {
        if (mt >= mtN) break;
#pragma unroll
        for (int nt = 0; nt < 4; nt++) {
            if (nt >= ntN) break;
            const int gmA = m0 + wm * 64 + mt * 16 + grp;
            const int gn  = n0 + wn * 32 + nt * 8 + 2 * qid;
            if (gn + 2 > N) continue;
#pragma unroll
            for (int half_ = 0; half_ < 2; half_++) {
                const int gm = gmA + half_ * 8;
                if (gm >= M) continue;
                const float v0 = acc[mt][nt][half_ * 2 + 0] * alpha;
                const float v1 = acc[mt][nt][half_ * 2 + 1] * alpha;
                if (OUT == 0) {
                    *reinterpret_cast<float2*>(Cf + (long)gm * ldc + gn) =
                        make_float2(v0, v1);
                } else if (OUT == 1) {
                    __half2 lo, hi = split_hi(v0, v1, lo);
                    *reinterpret_cast<__half2*>(Ch + (long)gm * ldc + gn) = hi;
                    *reinterpret_cast<__half2*>(Cl + (long)gm * ldc + gn) = lo;
                } else {
                    const int b1 = gn / XD, x = gn - b1 * XD;
                    const long addr = (long)b1 * sC + (long)gm * XD + x;
                    __half2 lo, hi = split_hi(v0, v1, lo);
                    *reinterpret_cast<__half2*>(Ch + addr) = hi;
                    *reinterpret_cast<__half2*>(Cl + addr) = lo;
                }
            }
        }
    }
}

// ---------------------------------------------------------------------------
// conversions
// ---------------------------------------------------------------------------
__global__ void split_rows(const float* __restrict__ in,
                           __half* __restrict__ oh, __half* __restrict__ ol,
                           int rows, int cols, int ldo)
{
    const int c4n = cols / 4;
    const long f = (long)blockIdx.x * blockDim.x + threadIdx.x;
    if (f < (long)rows * c4n) {
        const int row = (int)(f / c4n), c4 = (int)(f % c4n);
        const float4 v = *reinterpret_cast<const float4*>(in + (long)row * cols + c4 * 4);
        __half2 l0, h0 = split_hi(v.x, v.y, l0);
        __half2 l1, h1 = split_hi(v.z, v.w, l1);
        __half2* ph = reinterpret_cast<__half2*>(oh + (long)row * ldo + c4 * 4);
        __half2* pl = reinterpret_cast<__half2*>(ol + (long)row * ldo + c4 * 4);
        ph[0] = h0; ph[1] = h1;
        pl[0] = l0; pl[1] = l1;
    }
}

__global__ void split_transpose(const float* __restrict__ in,
                                __half* __restrict__ oh, __half* __restrict__ ol,
                                int R, int Cc, int ldo, long sIn, long sOut)
{
    __shared__ float t[32][33];
    const int b = blockIdx.z;
    in += (long)b * sIn; oh += (long)b * sOut; ol += (long)b * sOut;
    const int c0 = blockIdx.x * 32, r0 = blockIdx.y * 32;
#pragma unroll
    for (int i = 0; i < 4; i++) {
        const int r = r0 + threadIdx.y + 8 * i, c = c0 + threadIdx.x;
        t[threadIdx.y + 8 * i][threadIdx.x] =
            (r < R && c < Cc) ? in[(long)r * Cc + c] : 0.f;
    }
    __syncthreads();
#pragma unroll
    for (int i = 0; i < 4; i++) {
        const int c = c0 + threadIdx.y + 8 * i, r = r0 + threadIdx.x;
        if (c < Cc && r < R) {
            const float v = t[threadIdx.x][threadIdx.y + 8 * i];
            const __half h = __float2half(v);
            oh[(long)c * ldo + r] = h;
            ol[(long)c * ldo + r] = __float2half(v - __half2float(h));
        }
    }
}

__global__ void conv_H(const float* __restrict__ H,
                       __half* __restrict__ Hh, __half* __restrict__ Hl,
                       __half* __restrict__ HTh, __half* __restrict__ HTl)
{
    __shared__ float t[32][33];
    const int b = blockIdx.z;
    const float* in = H + (long)b * TT * HD;
    const int c0 = blockIdx.x * 32, r0 = blockIdx.y * 32;
#pragma unroll
    for (int i = 0; i < 4; i++) {
        const int r = r0 + threadIdx.y + 8 * i, c = c0 + threadIdx.x;
        float v = 0.f;
        if (r < TT) {
            v = in[(long)r * HD + c];
            const __half h = __float2half(v);
            Hh[(long)b * TT * HD + (long)r * HD + c] = h;
            Hl[(long)b * TT * HD + (long)r * HD + c] =
                __float2half(v - __half2float(h));
        }
        t[threadIdx.y + 8 * i][threadIdx.x] = v;
    }
    __syncthreads();
#pragma unroll
    for (int i = 0; i < 4; i++) {
        const int c = c0 + threadIdx.y + 8 * i, r = r0 + threadIdx.x;
        if (r < TT) {
            const float v = t[threadIdx.x][threadIdx.y + 8 * i];
            const __half h = __float2half(v);
            HTh[(long)b * HD * TTP + (long)c * TTP + r] = h;
            HTl[(long)b * HD * TTP + (long)c * TTP + r] =
                __float2half(v - __half2float(h));
        }
    }
}

// fused softmax with smem row cache: read S once, write P (fp16 hi only)
__global__ void __launch_bounds__(128) softmax_fused(
    const float* __restrict__ S, __half* __restrict__ oh)
{
    __shared__ float row[TT];
    __shared__ float sm[4], ss[4];
    const long r = blockIdx.x;
    const float4* p = reinterpret_cast<const float4*>(S + r * (long)TT);
    const int tid = threadIdx.x;

    float m = -3.0e38f, s = 0.f;
    for (int j = tid; j < TT / 4; j += 128) {
        const float4 v = p[j];
        *reinterpret_cast<float4*>(&row[j * 4]) = v;
        const float mv = fmaxf(fmaxf(v.x, v.y), fmaxf(v.z, v.w));
        if (mv > m) { s *= __expf(m - mv); m = mv; }
        s += __expf(v.x - m) + __expf(v.y - m) + __expf(v.z - m) + __expf(v.w - m);
    }
#pragma unroll
    for (int o = 16; o; o >>= 1) {
        const float m2 = __shfl_xor_sync(0xffffffffu, m, o);
        const float s2 = __shfl_xor_sync(0xffffffffu, s, o);
        const float M = fmaxf(m, m2);
        s = s * __expf(m - M) + s2 * __expf(m2 - M);
        m = M;
    }
    if ((tid & 31) == 0) { sm[tid >> 5] = m; ss[tid >> 5] = s; }
    __syncthreads();
    const float M = fmaxf(fmaxf(sm[0], sm[1]), fmaxf(sm[2], sm[3]));
    const float S_ = ss[0] * __expf(sm[0] - M) + ss[1] * __expf(sm[1] - M)
                   + ss[2] * __expf(sm[2] - M) + ss[3] * __expf(sm[3] - M);
    const float rv = 1.0f / S_;

    for (int j = tid; j < TT / 4; j += 128) {
        const float4 v = *reinterpret_cast<const float4*>(&row[j * 4]);
        const float f0 = __expf(v.x - M) * rv, f1 = __expf(v.y - M) * rv;
        const float f2 = __expf(v.z - M) * rv, f3 = __expf(v.w - M) * rv;
        __half2* ph = reinterpret_cast<__half2*>(oh + r * (long)TTP + j * 4);
        ph[0] = __halves2half2(__float2half(f0), __float2half(f1));
        ph[1] = __halves2half2(__float2half(f2), __float2half(f3));
    }
}

// ---------------------------------------------------------------------------
extern "C" void kernel_launch(void* const* d_in, const int* in_sizes, int n_in,
                              void* d_out, int out_size)
{
    const float* X  = (const float*)d_in[0];
    const float* H  = (const float*)d_in[1];
    const float* W1 = (const float*)d_in[2];
    const float* W2 = (const float*)d_in[3];
    float* out = (float*)d_out;

    float* S;
    cudaGetSymbolAddress((void**)&S, g_S);
    __half *W2h, *W2l, *XTh, *XTl, *Hh, *Hl, *HTh, *HTl, *W1Th, *W1Tl;
    __half *M1h, *M1l, *Gh, *Gl, *Ph;
    cudaGetSymbolAddress((void**)&W2h, g_W2h);   cudaGetSymbolAddress((void**)&W2l, g_W2l);
    cudaGetSymbolAddress((void**)&XTh, g_XTh);   cudaGetSymbolAddress((void**)&XTl, g_XTl);
    cudaGetSymbolAddress((void**)&Hh,  g_Hh);    cudaGetSymbolAddress((void**)&Hl,  g_Hl);
    cudaGetSymbolAddress((void**)&HTh, g_HTh);   cudaGetSymbolAddress((void**)&HTl, g_HTl);
    cudaGetSymbolAddress((void**)&W1Th, g_W1Th); cudaGetSymbolAddress((void**)&W1Tl, g_W1Tl);
    cudaGetSymbolAddress((void**)&M1h, g_M1h);   cudaGetSymbolAddress((void**)&M1l, g_M1l);
    cudaGetSymbolAddress((void**)&Gh,  g_Gh);    cudaGetSymbolAddress((void**)&Gl,  g_Gl);
    cudaGetSymbolAddress((void**)&Ph,  g_Ph);

    constexpr int SM128   = 2 * (2 * 128 * ROWST + 2 * 128 * ROWST) * 2;   // 81920
    constexpr int SM96    = 2 * (2 * 128 * ROWST + 2 *  96 * ROWST) * 2;   // 71680
    constexpr int SM96A1B1= 2 * (1 * 128 * ROWST + 1 *  96 * ROWST) * 2;   // 35840
    cudaFuncSetAttribute(gemm_h3<128,256,0,1,1,2>, cudaFuncAttributeMaxDynamicSharedMemorySize, SM128);
    cudaFuncSetAttribute(gemm_h3<128,256,2,1,1,2>, cudaFuncAttributeMaxDynamicSharedMemorySize, SM128);
    cudaFuncSetAttribute(gemm_h3< 96,192,1,1,1,2>, cudaFuncAttributeMaxDynamicSharedMemorySize, SM96);
    cudaFuncSetAttribute(gemm_h3< 96,192,0,0,0,3>, cudaFuncAttributeMaxDynamicSharedMemorySize, SM96A1B1);

    const float SCALE = (float)(1.0 / (sqrt((double)XD) * sqrt((double)HD)));

    // conversions
    {
        const long f = (long)CN * (TT / 4);
        split_rows<<<(unsigned)((f + 255) / 256), 256>>>(W2, W2h, W2l, CN, TT, TTP);
    }
    split_transpose<<<dim3(XD / 32, (TT + 31) / 32, BB), dim3(32, 8)>>>(
        X, XTh, XTl, TT, XD, TTP, (long)TT * XD, (long)XD * TTP);
    conv_H<<<dim3(HD / 32, (TT + 31) / 32, BB), dim3(32, 8)>>>(H, Hh, Hl, HTh, HTl);
    split_transpose<<<dim3(HD / 32, (XD + 31) / 32, 1), dim3(32, 8)>>>(
        W1, W1Th, W1Tl, XD, HD, XD, 0L, 0L);

    // K1 (merged): M1[(b,c,x)] = sum_t W2[c,t] * XT[(b,x),t]; scatter fp16
    gemm_h3<128,256,2,1,1,2><<<dim3(48, 3, 1), 256, SM128>>>(
        W2h, W2l, XTh, XTl, nullptr, M1h, M1l,
        CN, BB * XD, TT, TTP, TTP, 0,
        0L, 0L, (long)CN * XD, 1.0f);

    // K2 (merged): G[(b,c)][h] = SCALE * sum_x M1[(b,c),x] * W1T[h,x]; fp16 out
    gemm_h3<96,192,1,1,1,2><<<dim3(2, (BB * CN + 127) / 128, 1), 192, SM96>>>(
        M1h, M1l, W1Th, W1Tl, nullptr, Gh, Gl,
        BB * CN, HD, XD, XD, XD, HD,
        0L, 0L, 0L, SCALE);

    // K3 (batched): S[b] = G[b] @ H[b]^T; fp32 out
    gemm_h3<128,256,0,1,1,2><<<dim3(11, 3, BB), 256, SM128>>>(
        Gh, Gl, Hh, Hl, S, nullptr, nullptr,
        CN, TT, HD, HD, HD, TT,
        (long)CN * HD, (long)TT * HD, (long)CN * TT, 1.0f);

    // K4: fused softmax stats + P emit (fp16 hi only, smem row cache)
    softmax_fused<<<BB * CN, 128>>>(S, Ph);

    // K5 (batched): out[b] = P[b] @ H[b]; pure fp16 1-pass, BN=96, OCC=3
    gemm_h3<96,192,0,0,0,3><<<dim3(2, 3, BB), 192, SM96A1B1>>>(
        Ph, nullptr, HTh, nullptr, out, nullptr, nullptr,
        CN, HD, TT, TTP, TTP, HD,
        (long)CN * TTP, (long)HD * TTP, (long)CN * HD, 1.0f);
}